// round 11
// baseline (speedup 1.0000x reference)
#include <cuda_runtime.h>
#include <math.h>

// Problem constants
#define B_ 8
#define S_ 512
#define D_ 512
#define H_ 8
#define DK_ 64
#define DV_ 64
#define DFF_ 2048
#define L_ 6
#define M_ (B_ * S_)               // 4096 rows
#define X_ELEMS (M_ * D_)          // 2,097,152
#define ATTN_PER_LAYER ((long)B_ * H_ * S_ * S_)  // 16,777,216
#define WLD (D_ * D_)              // 262144
#define WF (D_ * DFF_)             // 1048576

// Device scratch (allocations are forbidden; use __device__ globals)
__device__ float g_x[X_ELEMS];
__device__ float g_xr[X_ELEMS];    // tf32-rounded copy of x (GEMM A input)
__device__ float g_q[X_ELEMS];
__device__ float g_k[X_ELEMS];
__device__ float g_v[X_ELEMS];
__device__ float g_ctx[X_ELEMS];
__device__ float g_tmp[X_ELEMS];
__device__ float g_h1[M_ * DFF_];
__device__ float g_pos[S_ * D_];
__device__ float g_wr[6 * (4 * WLD + 2 * WF)];  // tf32-rounded weights

// ---------------------------------------------------------------------------
// helpers
// ---------------------------------------------------------------------------
__device__ __forceinline__ unsigned tfc(unsigned x) {
    unsigned r;
    asm("cvt.rna.tf32.f32 %0, %1;" : "=r"(r) : "f"(__uint_as_float(x)));
    return r;
}
__device__ __forceinline__ float frnd(float x) {
    return __uint_as_float(tfc(__float_as_uint(x)));
}

__device__ __forceinline__ void mma8(float* d, const unsigned* a, const unsigned* b) {
    asm volatile(
        "mma.sync.aligned.m16n8k8.row.col.f32.tf32.tf32.f32 "
        "{%0,%1,%2,%3}, {%4,%5,%6,%7}, {%8,%9}, {%0,%1,%2,%3};"
        : "+f"(d[0]), "+f"(d[1]), "+f"(d[2]), "+f"(d[3])
        : "r"(a[0]), "r"(a[1]), "r"(a[2]), "r"(a[3]), "r"(b[0]), "r"(b[1]));
}

__device__ __forceinline__ void ldsm_x4(unsigned* r, unsigned addr) {
    asm volatile("ldmatrix.sync.aligned.m8n8.x4.shared.b16 {%0,%1,%2,%3}, [%4];"
                 : "=r"(r[0]), "=r"(r[1]), "=r"(r[2]), "=r"(r[3]) : "r"(addr));
}

__device__ __forceinline__ void cpa16(unsigned dst, const void* src) {
    asm volatile("cp.async.cg.shared.global [%0], [%1], 16;" :: "r"(dst), "l"(src));
}
__device__ __forceinline__ void cpa_commit() {
    asm volatile("cp.async.commit_group;" ::: "memory");
}
template <int N>
__device__ __forceinline__ void cpa_wait() {
    asm volatile("cp.async.wait_group %0;" :: "n"(N) : "memory");
}

// ---------------------------------------------------------------------------
// tf32 rounding copy (for weights)
// ---------------------------------------------------------------------------
__global__ void round_kernel(const float4* __restrict__ in,
                             float4* __restrict__ out, int n4) {
    int i = blockIdx.x * blockDim.x + threadIdx.x;
    if (i >= n4) return;
    float4 v = in[i];
    v.x = frnd(v.x); v.y = frnd(v.y); v.z = frnd(v.z); v.w = frnd(v.w);
    out[i] = v;
}

// ---------------------------------------------------------------------------
// Positional table (double precision to match numpy float64 path)
// ---------------------------------------------------------------------------
__global__ void pos_kernel(float* __restrict__ pos) {
    int idx = blockIdx.x * blockDim.x + threadIdx.x;
    if (idx >= S_ * D_) return;
    int s = idx >> 9;
    int d = idx & 511;
    double val = 0.0;
    if (s > 0) {
        double ang = (double)s * exp(-log(10000.0) * (2.0 * (double)d / (double)D_));
        val = (d & 1) ? cos(ang) : sin(ang);
    }
    pos[idx] = (float)val;
}

__global__ void add_pos_kernel(float* __restrict__ x, float* __restrict__ xr,
                               const float* __restrict__ enc,
                               const float* __restrict__ pos) {
    int idx = blockIdx.x * blockDim.x + threadIdx.x;
    if (idx >= X_ELEMS) return;
    int sd = idx & (S_ * D_ - 1);
    float v = enc[idx] + pos[sd];
    x[idx] = v;
    xr[idx] = frnd(v);
}

// ---------------------------------------------------------------------------
// TF32 tensor-core GEMM, BK-wide cp.async pipeline (BK=32, 3 stages).
//   C[m,n] = alpha * sum_k A[m,k] * (TB ? B[n,k] : B[k,n])  (+ epilogue)
// Inputs pre-rounded to tf32 except CVTA=true (cvt.rna A frags post-ldmatrix).
// ROUT=true: round outputs to tf32. epi: 0 none, 1 relu, 2 += R.
// ---------------------------------------------------------------------------
template <int BM, int BN, bool TB, int STAGES, int BK>
struct GCfg {
    static constexpr int ASTR = BK + 4;
    static constexpr int ABUF = BM * ASTR;
    static constexpr int BSTR = TB ? (BK + 4) : (BN + 8);
    static constexpr int BBUF = TB ? (BN * (BK + 4)) : (BK * (BN + 8));
    static constexpr int SMEM_BYTES = STAGES * (ABUF + BBUF) * 4;
};

template <int BM, int BN, bool TB, int STAGES, int BK, bool CVTA, bool ROUT>
__device__ __forceinline__ void gemm_body(
    float* __restrict__ smem,
    const float* __restrict__ A, int lda,
    const float* __restrict__ Bg, int ldb,
    float* __restrict__ C, int ldc,
    const float* __restrict__ R,
    int K, float alpha, int epi) {
    using CF = GCfg<BM, BN, TB, STAGES, BK>;
    constexpr int ASTR = CF::ASTR, ABUF = CF::ABUF;
    constexpr int BSTR = CF::BSTR, BBUF = CF::BBUF;
    constexpr int KF4 = BK / 4;               // float4 per row-chunk
    constexpr int AF = (BM * BK) / (4 * 256);
    constexpr int BF = (BN * BK) / (4 * 256);
    constexpr int WM = BM / 2, WN = BN / 4;
    constexpr int MT = WM / 16, NT = WN / 8;
    constexpr int NKS = BK / 8;

    const int tid = threadIdx.x;
    const int lane = tid & 31;
    const int warp = tid >> 5;
    const int g = lane >> 2;
    const int tg = lane & 3;
    const int wr = warp & 1;
    const int wc = warp >> 1;
    const int m0 = blockIdx.y * BM;
    const int n0 = blockIdx.x * BN;

    float* As = smem;
    float* Bs = smem + STAGES * ABUF;
    const unsigned as_u = (unsigned)__cvta_generic_to_shared(As);
    const unsigned bs_u = (unsigned)__cvta_generic_to_shared(Bs);

    const float* pA[AF];
    unsigned aoff[AF];
#pragma unroll
    for (int it = 0; it < AF; it++) {
        int f = tid + it * 256;
        int row = f / KF4, c4 = f % KF4;
        pA[it] = A + (long)(m0 + row) * lda + c4 * 4;
        aoff[it] = as_u + (unsigned)(row * ASTR + c4 * 4) * 4u;
    }
    const float* pB[BF];
    unsigned boff[BF];
    const long stepB = TB ? BK : (long)BK * ldb;
#pragma unroll
    for (int it = 0; it < BF; it++) {
        int f = tid + it * 256;
        if (TB) {
            int n = f / KF4, k4 = f % KF4;
            pB[it] = Bg + (long)(n0 + n) * ldb + k4 * 4;
            boff[it] = bs_u + (unsigned)(n * BSTR + k4 * 4) * 4u;
        } else {
            int row = f / (BN / 4), c4 = f % (BN / 4);
            pB[it] = Bg + (long)row * ldb + n0 + c4 * 4;
            boff[it] = bs_u + (unsigned)(row * BSTR + c4 * 4) * 4u;
        }
    }

    int slot_ld = 0;
    auto load_stage = [&]() {
        const unsigned ao = (unsigned)(slot_ld * ABUF) * 4u;
        const unsigned bo = (unsigned)(slot_ld * BBUF) * 4u;
#pragma unroll
        for (int it = 0; it < AF; it++) {
            cpa16(aoff[it] + ao, pA[it]);
            pA[it] += BK;
        }
#pragma unroll
        for (int it = 0; it < BF; it++) {
            cpa16(boff[it] + bo, pB[it]);
            pB[it] += stepB;
        }
        slot_ld = (slot_ld + 1 == STAGES) ? 0 : slot_ld + 1;
    };

    const unsigned a_base =
        as_u + (unsigned)(((wr * WM + (lane & 7) + 8 * ((lane >> 3) & 1)) * ASTR +
                           4 * (lane >> 4)) << 2);
    unsigned b_base = 0;
    if (TB) {
        b_base = bs_u + (unsigned)(((wc * WN + (lane & 7) + 8 * (lane >> 4)) * BSTR +
                                    4 * ((lane >> 3) & 1)) << 2);
    }

    float acc[MT][NT][4];
#pragma unroll
    for (int i = 0; i < MT; i++)
#pragma unroll
        for (int j = 0; j < NT; j++)
#pragma unroll
            for (int e = 0; e < 4; e++) acc[i][j][e] = 0.0f;

    const int nch = K / BK;
#pragma unroll
    for (int s = 0; s < STAGES - 1; s++) {
        if (s < nch) load_stage();
        cpa_commit();
    }

    int slot_cmp = 0;
    for (int c = 0; c < nch; c++) {
        cpa_wait<STAGES - 2>();
        __syncthreads();
        const unsigned abp = a_base + (unsigned)(slot_cmp * ABUF) * 4u;
        const unsigned bbp = b_base + (unsigned)(slot_cmp * BBUF) * 4u;
        const float* bbf = Bs + slot_cmp * BBUF;
        slot_cmp = (slot_cmp + 1 == STAGES) ? 0 : slot_cmp + 1;

#pragma unroll
        for (int ks = 0; ks < NKS; ks++) {
            unsigned afr[MT][4], bfr[NT][2];
#pragma unroll
            for (int i = 0; i < MT; i++) {
                ldsm_x4(afr[i], abp + i * (16 * ASTR * 4) + ks * 32);
                if (CVTA) {
#pragma unroll
                    for (int e = 0; e < 4; e++) afr[i][e] = tfc(afr[i][e]);
                }
            }
            if (TB) {
#pragma unroll
                for (int j = 0; j < NT; j += 2)
                    ldsm_x4(&bfr[j][0], bbp + j * (8 * BSTR * 4) + ks * 32);
            } else {
#pragma unroll
                for (int j = 0; j < NT; j++) {
                    int n = wc * WN + j * 8 + g;
                    bfr[j][0] = __float_as_uint(bbf[(ks * 8 + tg) * BSTR + n]);
                    bfr[j][1] = __float_as_uint(bbf[(ks * 8 + 4 + tg) * BSTR + n]);
                }
            }
#pragma unroll
            for (int i = 0; i < MT; i++)
#pragma unroll
                for (int j = 0; j < NT; j++) mma8(acc[i][j], afr[i], bfr[j]);
        }

        if (c + STAGES - 1 < nch) load_stage();
        cpa_commit();
    }

    // Epilogue
#pragma unroll
    for (int i = 0; i < MT; i++) {
        int r0 = m0 + wr * WM + i * 16 + g;
#pragma unroll
        for (int j = 0; j < NT; j++) {
            int col = n0 + wc * WN + j * 8 + tg * 2;
            float v0 = acc[i][j][0] * alpha;
            float v1 = acc[i][j][1] * alpha;
            float v2 = acc[i][j][2] * alpha;
            float v3 = acc[i][j][3] * alpha;
            if (epi == 1) {
                v0 = fmaxf(v0, 0.0f); v1 = fmaxf(v1, 0.0f);
                v2 = fmaxf(v2, 0.0f); v3 = fmaxf(v3, 0.0f);
            } else if (epi == 2) {
                v0 += R[(long)r0 * ldc + col];
                v1 += R[(long)r0 * ldc + col + 1];
                v2 += R[(long)(r0 + 8) * ldc + col];
                v3 += R[(long)(r0 + 8) * ldc + col + 1];
            }
            if (ROUT) {
                v0 = frnd(v0); v1 = frnd(v1); v2 = frnd(v2); v3 = frnd(v3);
            }
            float2 p01; p01.x = v0; p01.y = v1;
            float2 p23; p23.x = v2; p23.y = v3;
            *reinterpret_cast<float2*>(&C[(long)r0 * ldc + col]) = p01;
            *reinterpret_cast<float2*>(&C[(long)(r0 + 8) * ldc + col]) = p23;
        }
    }
}

template <int BM, int BN, bool TB, int STAGES, int BK, bool CVTA, bool ROUT>
__global__ void __launch_bounds__(256, 2)
gemm_cp(const float* __restrict__ A, int lda, long sAb, long sAh,
        const float* __restrict__ Bg, int ldb, long sBb, long sBh,
        float* __restrict__ C, int ldc, long sCb, long sCh,
        const float* __restrict__ R,
        int K, float alpha, int epi, int hdiv) {
    extern __shared__ float smem[];
    const int z = blockIdx.z;
    const int zb = z / hdiv;
    const int zh = z % hdiv;
    gemm_body<BM, BN, TB, STAGES, BK, CVTA, ROUT>(
        smem,
        A + (long)zb * sAb + (long)zh * sAh, lda,
        Bg + (long)zb * sBb + (long)zh * sBh, ldb,
        C + (long)zb * sCb + (long)zh * sCh, ldc,
        R, K, alpha, epi);
}

// Fused Q/K/V projection: blockIdx.z selects the weight/output pair.
__global__ void __launch_bounds__(256, 2)
qkv_cp(const float* __restrict__ x,
       const float* __restrict__ Wq, const float* __restrict__ Wk,
       const float* __restrict__ Wv,
       float* __restrict__ q, float* __restrict__ k, float* __restrict__ v) {
    extern __shared__ float smem[];
    const int z = blockIdx.z;
    const float* W = (z == 0) ? Wq : (z == 1) ? Wk : Wv;
    float* C = (z == 0) ? q : (z == 1) ? k : v;
    gemm_body<128, 128, false, 3, 32, false, true>(smem, x, D_, W, D_, C, D_,
                                                   nullptr, D_, 1.0f, 0);
}

// ---------------------------------------------------------------------------
// In-place row softmax; 128 threads, float4 per thread, shuffle reductions.
// ---------------------------------------------------------------------------
__global__ void __launch_bounds__(128)
softmax_kernel(float* __restrict__ attn, const int* __restrict__ mask) {
    const int row = blockIdx.x;
    const int b = row >> 12;
    const int t = threadIdx.x;
    float4* p = reinterpret_cast<float4*>(attn + (long)row * S_);
    const int4* mp = reinterpret_cast<const int4*>(mask + b * S_);

    float4 v = p[t];
    int4 mm = mp[t];
    if (mm.x == 0) v.x = -1e9f;
    if (mm.y == 0) v.y = -1e9f;
    if (mm.z == 0) v.z = -1e9f;
    if (mm.w == 0) v.w = -1e9f;

    float mx = fmaxf(fmaxf(v.x, v.y), fmaxf(v.z, v.w));
#pragma unroll
    for (int o = 16; o; o >>= 1) mx = fmaxf(mx, __shfl_xor_sync(0xffffffffu, mx, o));
    __shared__ float sm[4], ss[4];
    if ((t & 31) == 0) sm[t >> 5] = mx;
    __syncthreads();
    mx = fmaxf(fmaxf(sm[0], sm[1]), fmaxf(sm[2], sm[3]));

    float4 e;
    e.x = __expf(v.x - mx);
    e.y = __expf(v.y - mx);
    e.z = __expf(v.z - mx);
    e.w = __expf(v.w - mx);
    float s = e.x + e.y + e.z + e.w;
#pragma unroll
    for (int o = 16; o; o >>= 1) s += __shfl_xor_sync(0xffffffffu, s, o);
    if ((t & 31) == 0) ss[t >> 5] = s;
    __syncthreads();
    s = ss[0] + ss[1] + ss[2] + ss[3];
    const float inv = 1.0f / s;
    e.x *= inv; e.y *= inv; e.z *= inv; e.w *= inv;
    p[t] = e;
}

// ---------------------------------------------------------------------------
// LayerNorm over last dim (512); dual output (fp32 + tf32-rounded)
// ---------------------------------------------------------------------------
__global__ void ln_kernel(const float* __restrict__ in,
                          const float* __restrict__ g,
                          const float* __restrict__ bb,
                          float* __restrict__ out,
                          float* __restrict__ outr) {
    const int row = blockIdx.x;
    const float* p = in + (long)row * D_;
    const int t = threadIdx.x;

    float x0 = p[t];
    float x1 = p[t + 256];

    __shared__ float red[256];
    red[t] = x0 + x1;
    __syncthreads();
#pragma unroll
    for (int s = 128; s > 0; s >>= 1) {
        if (t < s) red[t] += red[t + s];
        __syncthreads();
    }
    const float mean = red[0] * (1.0f / D_);
    __syncthreads();

    float d0 = x0 - mean;
    float d1 = x1 - mean;
    red[t] = d0 * d0 + d1 * d1;
    __syncthreads();
#pragma unroll
    for (int s = 128; s > 0; s >>= 1) {
        if (t < s) red[t] += red[t + s];
        __syncthreads();
    }
    const float var = red[0] * (1.0f / D_);
    const float rs = rsqrtf(var + 1e-5f);

    float o0 = d0 * rs * g[t] + bb[t];
    float o1 = d1 * rs * g[t + 256] + bb[t + 256];
    float* o = out + (long)row * D_;
    o[t] = o0;
    o[t + 256] = o1;
    float* orr = outr + (long)row * D_;
    orr[t] = frnd(o0);
    orr[t + 256] = frnd(o1);
}

// ---------------------------------------------------------------------------
extern "C" void kernel_launch(void* const* d_in, const int* in_sizes, int n_in,
                              void* d_out, int out_size) {
    const float* enc = (const float*)d_in[0];
    const int* mask = (const int*)d_in[1];
    const float* Wq = (const float*)d_in[2];
    const float* Wk = (const float*)d_in[3];
    const float* Wv = (const float*)d_in[4];
    const float* Wo = (const float*)d_in[5];
    const float* ln1g = (const float*)d_in[6];
    const float* ln1b = (const float*)d_in[7];
    const float* W1 = (const float*)d_in[8];
    const float* W2 = (const float*)d_in[9];
    const float* ln2g = (const float*)d_in[10];
    const float* ln2b = (const float*)d_in[11];

    float *x, *xr, *q, *k, *v, *ctx, *tmp, *h1, *pos, *wr;
    cudaGetSymbolAddress((void**)&x, g_x);
    cudaGetSymbolAddress((void**)&xr, g_xr);
    cudaGetSymbolAddress((void**)&q, g_q);
    cudaGetSymbolAddress((void**)&k, g_k);
    cudaGetSymbolAddress((void**)&v, g_v);
    cudaGetSymbolAddress((void**)&ctx, g_ctx);
    cudaGetSymbolAddress((void**)&tmp, g_tmp);
    cudaGetSymbolAddress((void**)&h1, g_h1);
    cudaGetSymbolAddress((void**)&pos, g_pos);
    cudaGetSymbolAddress((void**)&wr, g_wr);

    float* Wq_r = wr;
    float* Wk_r = Wq_r + 6 * WLD;
    float* Wv_r = Wk_r + 6 * WLD;
    float* Wo_r = Wv_r + 6 * WLD;
    float* W1_r = Wo_r + 6 * WLD;
    float* W2_r = W1_r + 6 * WF;

    float* out_x = (float*)d_out;
    float* out_attn = out_x + X_ELEMS;

    constexpr int SM_PROJ = GCfg<128, 128, false, 3, 32>::SMEM_BYTES;  // 107520
    constexpr int SM_SCOR = GCfg<128, 128, true, 3, 32>::SMEM_BYTES;   // 110592
    constexpr int SM_N64  = GCfg<128, 64, false, 3, 32>::SMEM_BYTES;   // 82944
    cudaFuncSetAttribute(gemm_cp<128, 128, false, 3, 32, false, true>,
                         cudaFuncAttributeMaxDynamicSharedMemorySize, SM_PROJ);
    cudaFuncSetAttribute(gemm_cp<128, 128, true, 3, 32, false, false>,
                         cudaFuncAttributeMaxDynamicSharedMemorySize, SM_SCOR);
    cudaFuncSetAttribute(gemm_cp<128, 64, false, 3, 32, true, true>,
                         cudaFuncAttributeMaxDynamicSharedMemorySize, SM_N64);
    cudaFuncSetAttribute(gemm_cp<128, 64, false, 3, 32, false, false>,
                         cudaFuncAttributeMaxDynamicSharedMemorySize, SM_N64);
    cudaFuncSetAttribute(qkv_cp,
                         cudaFuncAttributeMaxDynamicSharedMemorySize, SM_PROJ);

    // Round all weights to tf32 once per launch
    round_kernel<<<(6 * WLD / 4 + 255) / 256, 256>>>(
        (const float4*)Wq, (float4*)Wq_r, 6 * WLD / 4);
    round_kernel<<<(6 * WLD / 4 + 255) / 256, 256>>>(
        (const float4*)Wk, (float4*)Wk_r, 6 * WLD / 4);
    round_kernel<<<(6 * WLD / 4 + 255) / 256, 256>>>(
        (const float4*)Wv, (float4*)Wv_r, 6 * WLD / 4);
    round_kernel<<<(6 * WLD / 4 + 255) / 256, 256>>>(
        (const float4*)Wo, (float4*)Wo_r, 6 * WLD / 4);
    round_kernel<<<(6 * WF / 4 + 255) / 256, 256>>>(
        (const float4*)W1, (float4*)W1_r, 6 * WF / 4);
    round_kernel<<<(6 * WF / 4 + 255) / 256, 256>>>(
        (const float4*)W2, (float4*)W2_r, 6 * WF / 4);

    pos_kernel<<<(S_ * D_ + 255) / 256, 256>>>(pos);
    add_pos_kernel<<<(X_ELEMS + 255) / 256, 256>>>(x, xr, enc, pos);

    for (int l = 0; l < L_; l++) {
        float* attn_l = out_attn + (long)l * ATTN_PER_LAYER;

        // Fused Q,K,V projections (rounded outputs)
        qkv_cp<<<dim3(4, 32, 3), 256, SM_PROJ>>>(
            xr, Wq_r + l * WLD, Wk_r + l * WLD, Wv_r + l * WLD, q, k, v);

        // Scores: per (b,h): Q[512,64] @ K^T * (1/8) -> attn region (exact out)
        gemm_cp<128, 128, true, 3, 32, false, false>
            <<<dim3(4, 4, B_ * H_), 256, SM_SCOR>>>(
            q, D_, (long)S_ * D_, DK_,
            k, D_, (long)S_ * D_, DK_,
            attn_l, S_, (long)H_ * S_ * S_, (long)S_ * S_,
            nullptr, DK_, 0.125f, 0, H_);

        // Softmax (in place, applies pad mask)
        softmax_kernel<<<B_ * H_ * S_, 128>>>(attn_l, mask);

        // ctx: per (b,h): attn[512,512] @ V[512,64] (A needs cvt; rounded out)
        gemm_cp<128, 64, false, 3, 32, true, true>
            <<<dim3(1, 4, B_ * H_), 256, SM_N64>>>(
            attn_l, S_, (long)H_ * S_ * S_, (long)S_ * S_,
            v, D_, (long)S_ * D_, DV_,
            ctx, D_, (long)S_ * D_, DV_,
            nullptr, S_, 1.0f, 0, H_);

        // Wo projection + residual(x fp32), then LN1 -> (x, xr)
        // BN=64 tiles -> 256 CTAs (fills 148 SMs; 128-CTA grid left SMs idle)
        gemm_cp<128, 64, false, 3, 32, false, false>
            <<<dim3(8, 32, 1), 256, SM_N64>>>(
            ctx, D_, 0, 0, Wo_r + l * WLD, D_, 0, 0, tmp, D_, 0, 0, x, D_,
            1.0f, 2, 1);
        ln_kernel<<<M_, 256>>>(tmp, ln1g + l * D_, ln1b + l * D_, x, xr);

        // FFN: relu(xr @ W1) (rounded) @ W2 + x, then LN2 -> (x, xr)
        gemm_cp<128, 128, false, 3, 32, false, true>
            <<<dim3(16, 32, 1), 256, SM_PROJ>>>(
            xr, D_, 0, 0, W1_r + l * WF, DFF_, 0, 0, h1, DFF_, 0, 0, nullptr, D_,
            1.0f, 1, 1);
        gemm_cp<128, 64, false, 3, 32, false, false>
            <<<dim3(8, 32, 1), 256, SM_N64>>>(
            h1, DFF_, 0, 0, W2_r + l * WF, D_, 0, 0, tmp, D_, 0, 0, x, DFF_,
            1.0f, 2, 1);
        ln_kernel<<<M_, 256>>>(tmp, ln2g + l * D_, ln2b + l * D_, x, xr);
    }

    cudaMemcpyAsync(out_x, x, (size_t)X_ELEMS * sizeof(float),
                    cudaMemcpyDeviceToDevice, 0);
}

// round 12
// speedup vs baseline: 1.1021x; 1.1021x over previous
#include <cuda_runtime.h>
#include <math.h>

// Problem constants
#define B_ 8
#define S_ 512
#define D_ 512
#define H_ 8
#define DK_ 64
#define DV_ 64
#define DFF_ 2048
#define L_ 6
#define M_ (B_ * S_)               // 4096 rows
#define X_ELEMS (M_ * D_)          // 2,097,152
#define ATTN_PER_LAYER ((long)B_ * H_ * S_ * S_)  // 16,777,216
#define WLD (D_ * D_)              // 262144
#define WF (D_ * DFF_)             // 1048576

// Device scratch (allocations are forbidden; use __device__ globals)
__device__ float g_x[X_ELEMS];
__device__ float g_xr[X_ELEMS];    // tf32-rounded copy of x (GEMM A input)
__device__ float g_q[X_ELEMS];     // q; reused as split-K partial buffer later
__device__ float g_k[X_ELEMS];
__device__ float g_v[X_ELEMS];
__device__ float g_ctx[X_ELEMS];
__device__ float g_tmp[X_ELEMS];
__device__ float g_h1[M_ * DFF_];
__device__ float g_pos[S_ * D_];
__device__ float g_wr[6 * (4 * WLD + 2 * WF)];  // tf32-rounded weights

// ---------------------------------------------------------------------------
// helpers
// ---------------------------------------------------------------------------
__device__ __forceinline__ unsigned tfc(unsigned x) {
    unsigned r;
    asm("cvt.rna.tf32.f32 %0, %1;" : "=r"(r) : "f"(__uint_as_float(x)));
    return r;
}
__device__ __forceinline__ float frnd(float x) {
    return __uint_as_float(tfc(__float_as_uint(x)));
}

__device__ __forceinline__ void mma8(float* d, const unsigned* a, const unsigned* b) {
    asm volatile(
        "mma.sync.aligned.m16n8k8.row.col.f32.tf32.tf32.f32 "
        "{%0,%1,%2,%3}, {%4,%5,%6,%7}, {%8,%9}, {%0,%1,%2,%3};"
        : "+f"(d[0]), "+f"(d[1]), "+f"(d[2]), "+f"(d[3])
        : "r"(a[0]), "r"(a[1]), "r"(a[2]), "r"(a[3]), "r"(b[0]), "r"(b[1]));
}

__device__ __forceinline__ void ldsm_x4(unsigned* r, unsigned addr) {
    asm volatile("ldmatrix.sync.aligned.m8n8.x4.shared.b16 {%0,%1,%2,%3}, [%4];"
                 : "=r"(r[0]), "=r"(r[1]), "=r"(r[2]), "=r"(r[3]) : "r"(addr));
}

__device__ __forceinline__ void cpa16(unsigned dst, const void* src) {
    asm volatile("cp.async.cg.shared.global [%0], [%1], 16;" :: "r"(dst), "l"(src));
}
__device__ __forceinline__ void cpa_commit() {
    asm volatile("cp.async.commit_group;" ::: "memory");
}
template <int N>
__device__ __forceinline__ void cpa_wait() {
    asm volatile("cp.async.wait_group %0;" :: "n"(N) : "memory");
}

// ---------------------------------------------------------------------------
// tf32 rounding copy (for weights)
// ---------------------------------------------------------------------------
__global__ void round_kernel(const float4* __restrict__ in,
                             float4* __restrict__ out, int n4) {
    int i = blockIdx.x * blockDim.x + threadIdx.x;
    if (i >= n4) return;
    float4 v = in[i];
    v.x = frnd(v.x); v.y = frnd(v.y); v.z = frnd(v.z); v.w = frnd(v.w);
    out[i] = v;
}

// ---------------------------------------------------------------------------
// Positional table (double precision to match numpy float64 path)
// ---------------------------------------------------------------------------
__global__ void pos_kernel(float* __restrict__ pos) {
    int idx = blockIdx.x * blockDim.x + threadIdx.x;
    if (idx >= S_ * D_) return;
    int s = idx >> 9;
    int d = idx & 511;
    double val = 0.0;
    if (s > 0) {
        double ang = (double)s * exp(-log(10000.0) * (2.0 * (double)d / (double)D_));
        val = (d & 1) ? cos(ang) : sin(ang);
    }
    pos[idx] = (float)val;
}

__global__ void add_pos_kernel(float* __restrict__ x, float* __restrict__ xr,
                               const float* __restrict__ enc,
                               const float* __restrict__ pos) {
    int idx = blockIdx.x * blockDim.x + threadIdx.x;
    if (idx >= X_ELEMS) return;
    int sd = idx & (S_ * D_ - 1);
    float v = enc[idx] + pos[sd];
    x[idx] = v;
    xr[idx] = frnd(v);
}

// ---------------------------------------------------------------------------
// TF32 tensor-core GEMM, BK-wide cp.async pipeline (BK=32, 3 stages).
//   C[m,n] = alpha * sum_k A[m,k] * (TB ? B[n,k] : B[k,n])  (+ epilogue)
// Inputs pre-rounded to tf32 except CVTA=true (cvt.rna A frags post-ldmatrix).
// ROUT=true: round outputs to tf32. epi: 0 none, 1 relu, 2 += R.
// ---------------------------------------------------------------------------
template <int BM, int BN, bool TB, int STAGES, int BK>
struct GCfg {
    static constexpr int ASTR = BK + 4;
    static constexpr int ABUF = BM * ASTR;
    static constexpr int BSTR = TB ? (BK + 4) : (BN + 8);
    static constexpr int BBUF = TB ? (BN * (BK + 4)) : (BK * (BN + 8));
    static constexpr int SMEM_BYTES = STAGES * (ABUF + BBUF) * 4;
};

template <int BM, int BN, bool TB, int STAGES, int BK, bool CVTA, bool ROUT>
__device__ __forceinline__ void gemm_body(
    float* __restrict__ smem,
    const float* __restrict__ A, int lda,
    const float* __restrict__ Bg, int ldb,
    float* __restrict__ C, int ldc,
    const float* __restrict__ R,
    int K, float alpha, int epi) {
    using CF = GCfg<BM, BN, TB, STAGES, BK>;
    constexpr int ASTR = CF::ASTR, ABUF = CF::ABUF;
    constexpr int BSTR = CF::BSTR, BBUF = CF::BBUF;
    constexpr int KF4 = BK / 4;               // float4 per row-chunk
    constexpr int AF = (BM * BK) / (4 * 256);
    constexpr int BF = (BN * BK) / (4 * 256);
    constexpr int WM = BM / 2, WN = BN / 4;
    constexpr int MT = WM / 16, NT = WN / 8;
    constexpr int NKS = BK / 8;

    const int tid = threadIdx.x;
    const int lane = tid & 31;
    const int warp = tid >> 5;
    const int g = lane >> 2;
    const int tg = lane & 3;
    const int wr = warp & 1;
    const int wc = warp >> 1;
    const int m0 = blockIdx.y * BM;
    const int n0 = blockIdx.x * BN;

    float* As = smem;
    float* Bs = smem + STAGES * ABUF;
    const unsigned as_u = (unsigned)__cvta_generic_to_shared(As);
    const unsigned bs_u = (unsigned)__cvta_generic_to_shared(Bs);

    const float* pA[AF];
    unsigned aoff[AF];
#pragma unroll
    for (int it = 0; it < AF; it++) {
        int f = tid + it * 256;
        int row = f / KF4, c4 = f % KF4;
        pA[it] = A + (long)(m0 + row) * lda + c4 * 4;
        aoff[it] = as_u + (unsigned)(row * ASTR + c4 * 4) * 4u;
    }
    const float* pB[BF];
    unsigned boff[BF];
    const long stepB = TB ? BK : (long)BK * ldb;
#pragma unroll
    for (int it = 0; it < BF; it++) {
        int f = tid + it * 256;
        if (TB) {
            int n = f / KF4, k4 = f % KF4;
            pB[it] = Bg + (long)(n0 + n) * ldb + k4 * 4;
            boff[it] = bs_u + (unsigned)(n * BSTR + k4 * 4) * 4u;
        } else {
            int row = f / (BN / 4), c4 = f % (BN / 4);
            pB[it] = Bg + (long)row * ldb + n0 + c4 * 4;
            boff[it] = bs_u + (unsigned)(row * BSTR + c4 * 4) * 4u;
        }
    }

    int slot_ld = 0;
    auto load_stage = [&]() {
        const unsigned ao = (unsigned)(slot_ld * ABUF) * 4u;
        const unsigned bo = (unsigned)(slot_ld * BBUF) * 4u;
#pragma unroll
        for (int it = 0; it < AF; it++) {
            cpa16(aoff[it] + ao, pA[it]);
            pA[it] += BK;
        }
#pragma unroll
        for (int it = 0; it < BF; it++) {
            cpa16(boff[it] + bo, pB[it]);
            pB[it] += stepB;
        }
        slot_ld = (slot_ld + 1 == STAGES) ? 0 : slot_ld + 1;
    };

    const unsigned a_base =
        as_u + (unsigned)(((wr * WM + (lane & 7) + 8 * ((lane >> 3) & 1)) * ASTR +
                           4 * (lane >> 4)) << 2);
    unsigned b_base = 0;
    if (TB) {
        b_base = bs_u + (unsigned)(((wc * WN + (lane & 7) + 8 * (lane >> 4)) * BSTR +
                                    4 * ((lane >> 3) & 1)) << 2);
    }

    float acc[MT][NT][4];
#pragma unroll
    for (int i = 0; i < MT; i++)
#pragma unroll
        for (int j = 0; j < NT; j++)
#pragma unroll
            for (int e = 0; e < 4; e++) acc[i][j][e] = 0.0f;

    const int nch = K / BK;
#pragma unroll
    for (int s = 0; s < STAGES - 1; s++) {
        if (s < nch) load_stage();
        cpa_commit();
    }

    int slot_cmp = 0;
    for (int c = 0; c < nch; c++) {
        cpa_wait<STAGES - 2>();
        __syncthreads();
        const unsigned abp = a_base + (unsigned)(slot_cmp * ABUF) * 4u;
        const unsigned bbp = b_base + (unsigned)(slot_cmp * BBUF) * 4u;
        const float* bbf = Bs + slot_cmp * BBUF;
        slot_cmp = (slot_cmp + 1 == STAGES) ? 0 : slot_cmp + 1;

#pragma unroll
        for (int ks = 0; ks < NKS; ks++) {
            unsigned afr[MT][4], bfr[NT][2];
#pragma unroll
            for (int i = 0; i < MT; i++) {
                ldsm_x4(afr[i], abp + i * (16 * ASTR * 4) + ks * 32);
                if (CVTA) {
#pragma unroll
                    for (int e = 0; e < 4; e++) afr[i][e] = tfc(afr[i][e]);
                }
            }
            if (TB) {
#pragma unroll
                for (int j = 0; j < NT; j += 2)
                    ldsm_x4(&bfr[j][0], bbp + j * (8 * BSTR * 4) + ks * 32);
            } else {
#pragma unroll
                for (int j = 0; j < NT; j++) {
                    int n = wc * WN + j * 8 + g;
                    bfr[j][0] = __float_as_uint(bbf[(ks * 8 + tg) * BSTR + n]);
                    bfr[j][1] = __float_as_uint(bbf[(ks * 8 + 4 + tg) * BSTR + n]);
                }
            }
#pragma unroll
            for (int i = 0; i < MT; i++)
#pragma unroll
                for (int j = 0; j < NT; j++) mma8(acc[i][j], afr[i], bfr[j]);
        }

        if (c + STAGES - 1 < nch) load_stage();
        cpa_commit();
    }

    // Epilogue
#pragma unroll
    for (int i = 0; i < MT; i++) {
        int r0 = m0 + wr * WM + i * 16 + g;
#pragma unroll
        for (int j = 0; j < NT; j++) {
            int col = n0 + wc * WN + j * 8 + tg * 2;
            float v0 = acc[i][j][0] * alpha;
            float v1 = acc[i][j][1] * alpha;
            float v2 = acc[i][j][2] * alpha;
            float v3 = acc[i][j][3] * alpha;
            if (epi == 1) {
                v0 = fmaxf(v0, 0.0f); v1 = fmaxf(v1, 0.0f);
                v2 = fmaxf(v2, 0.0f); v3 = fmaxf(v3, 0.0f);
            } else if (epi == 2) {
                v0 += R[(long)r0 * ldc + col];
                v1 += R[(long)r0 * ldc + col + 1];
                v2 += R[(long)(r0 + 8) * ldc + col];
                v3 += R[(long)(r0 + 8) * ldc + col + 1];
            }
            if (ROUT) {
                v0 = frnd(v0); v1 = frnd(v1); v2 = frnd(v2); v3 = frnd(v3);
            }
            float2 p01; p01.x = v0; p01.y = v1;
            float2 p23; p23.x = v2; p23.y = v3;
            *reinterpret_cast<float2*>(&C[(long)r0 * ldc + col]) = p01;
            *reinterpret_cast<float2*>(&C[(long)(r0 + 8) * ldc + col]) = p23;
        }
    }
}

template <int BM, int BN, bool TB, int STAGES, int BK, bool CVTA, bool ROUT>
__global__ void __launch_bounds__(256, 2)
gemm_cp(const float* __restrict__ A, int lda, long sAb, long sAh,
        const float* __restrict__ Bg, int ldb, long sBb, long sBh,
        float* __restrict__ C, int ldc, long sCb, long sCh,
        const float* __restrict__ R,
        int K, float alpha, int epi, int hdiv) {
    extern __shared__ float smem[];
    const int z = blockIdx.z;
    const int zb = z / hdiv;
    const int zh = z % hdiv;
    gemm_body<BM, BN, TB, STAGES, BK, CVTA, ROUT>(
        smem,
        A + (long)zb * sAb + (long)zh * sAh, lda,
        Bg + (long)zb * sBb + (long)zh * sBh, ldb,
        C + (long)zb * sCb + (long)zh * sCh, ldc,
        R, K, alpha, epi);
}

// Fused Q/K/V projection: blockIdx.z selects the weight/output pair.
__global__ void __launch_bounds__(256, 2)
qkv_cp(const float* __restrict__ x,
       const float* __restrict__ Wq, const float* __restrict__ Wk,
       const float* __restrict__ Wv,
       float* __restrict__ q, float* __restrict__ k, float* __restrict__ v) {
    extern __shared__ float smem[];
    const int z = blockIdx.z;
    const float* W = (z == 0) ? Wq : (z == 1) ? Wk : Wv;
    float* C = (z == 0) ? q : (z == 1) ? k : v;
    gemm_body<128, 128, false, 3, 32, false, true>(smem, x, D_, W, D_, C, D_,
                                                   nullptr, D_, 1.0f, 0);
}

// ---------------------------------------------------------------------------
// In-place row softmax; 128 threads, float4 per thread, shuffle reductions.
// ---------------------------------------------------------------------------
__global__ void __launch_bounds__(128)
softmax_kernel(float* __restrict__ attn, const int* __restrict__ mask) {
    const int row = blockIdx.x;
    const int b = row >> 12;
    const int t = threadIdx.x;
    float4* p = reinterpret_cast<float4*>(attn + (long)row * S_);
    const int4* mp = reinterpret_cast<const int4*>(mask + b * S_);

    float4 v = p[t];
    int4 mm = mp[t];
    if (mm.x == 0) v.x = -1e9f;
    if (mm.y == 0) v.y = -1e9f;
    if (mm.z == 0) v.z = -1e9f;
    if (mm.w == 0) v.w = -1e9f;

    float mx = fmaxf(fmaxf(v.x, v.y), fmaxf(v.z, v.w));
#pragma unroll
    for (int o = 16; o; o >>= 1) mx = fmaxf(mx, __shfl_xor_sync(0xffffffffu, mx, o));
    __shared__ float sm[4], ss[4];
    if ((t & 31) == 0) sm[t >> 5] = mx;
    __syncthreads();
    mx = fmaxf(fmaxf(sm[0], sm[1]), fmaxf(sm[2], sm[3]));

    float4 e;
    e.x = __expf(v.x - mx);
    e.y = __expf(v.y - mx);
    e.z = __expf(v.z - mx);
    e.w = __expf(v.w - mx);
    float s = e.x + e.y + e.z + e.w;
#pragma unroll
    for (int o = 16; o; o >>= 1) s += __shfl_xor_sync(0xffffffffu, s, o);
    if ((t & 31) == 0) ss[t >> 5] = s;
    __syncthreads();
    s = ss[0] + ss[1] + ss[2] + ss[3];
    const float inv = 1.0f / s;
    e.x *= inv; e.y *= inv; e.z *= inv; e.w *= inv;
    p[t] = e;
}

// ---------------------------------------------------------------------------
// LayerNorm over last dim (512); input = p0 + p1 + residual (split-K reduce
// fused); dual output (fp32 + tf32-rounded).
// ---------------------------------------------------------------------------
__global__ void ln3_kernel(const float* __restrict__ p0,
                           const float* __restrict__ p1,
                           const float* __restrict__ res,
                           const float* __restrict__ g,
                           const float* __restrict__ bb,
                           float* __restrict__ out,
                           float* __restrict__ outr) {
    const int row = blockIdx.x;
    const long base = (long)row * D_;
    const int t = threadIdx.x;

    float x0 = (p0[base + t] + p1[base + t]) + res[base + t];
    float x1 = (p0[base + t + 256] + p1[base + t + 256]) + res[base + t + 256];

    __shared__ float red[256];
    red[t] = x0 + x1;
    __syncthreads();
#pragma unroll
    for (int s = 128; s > 0; s >>= 1) {
        if (t < s) red[t] += red[t + s];
        __syncthreads();
    }
    const float mean = red[0] * (1.0f / D_);
    __syncthreads();

    float d0 = x0 - mean;
    float d1 = x1 - mean;
    red[t] = d0 * d0 + d1 * d1;
    __syncthreads();
#pragma unroll
    for (int s = 128; s > 0; s >>= 1) {
        if (t < s) red[t] += red[t + s];
        __syncthreads();
    }
    const float var = red[0] * (1.0f / D_);
    const float rs = rsqrtf(var + 1e-5f);

    float o0 = d0 * rs * g[t] + bb[t];
    float o1 = d1 * rs * g[t + 256] + bb[t + 256];
    out[base + t] = o0;
    out[base + t + 256] = o1;
    outr[base + t] = frnd(o0);
    outr[base + t + 256] = frnd(o1);
}

// ---------------------------------------------------------------------------
extern "C" void kernel_launch(void* const* d_in, const int* in_sizes, int n_in,
                              void* d_out, int out_size) {
    const float* enc = (const float*)d_in[0];
    const int* mask = (const int*)d_in[1];
    const float* Wq = (const float*)d_in[2];
    const float* Wk = (const float*)d_in[3];
    const float* Wv = (const float*)d_in[4];
    const float* Wo = (const float*)d_in[5];
    const float* ln1g = (const float*)d_in[6];
    const float* ln1b = (const float*)d_in[7];
    const float* W1 = (const float*)d_in[8];
    const float* W2 = (const float*)d_in[9];
    const float* ln2g = (const float*)d_in[10];
    const float* ln2b = (const float*)d_in[11];

    float *x, *xr, *q, *k, *v, *ctx, *tmp, *h1, *pos, *wr;
    cudaGetSymbolAddress((void**)&x, g_x);
    cudaGetSymbolAddress((void**)&xr, g_xr);
    cudaGetSymbolAddress((void**)&q, g_q);
    cudaGetSymbolAddress((void**)&k, g_k);
    cudaGetSymbolAddress((void**)&v, g_v);
    cudaGetSymbolAddress((void**)&ctx, g_ctx);
    cudaGetSymbolAddress((void**)&tmp, g_tmp);
    cudaGetSymbolAddress((void**)&h1, g_h1);
    cudaGetSymbolAddress((void**)&pos, g_pos);
    cudaGetSymbolAddress((void**)&wr, g_wr);

    float* Wq_r = wr;
    float* Wk_r = Wq_r + 6 * WLD;
    float* Wv_r = Wk_r + 6 * WLD;
    float* Wo_r = Wv_r + 6 * WLD;
    float* W1_r = Wo_r + 6 * WLD;
    float* W2_r = W1_r + 6 * WF;

    float* out_x = (float*)d_out;
    float* out_attn = out_x + X_ELEMS;

    constexpr int SM_PROJ = GCfg<128, 128, false, 3, 32>::SMEM_BYTES;  // 107520
    constexpr int SM_SCOR = GCfg<128, 128, true, 3, 32>::SMEM_BYTES;   // 110592
    constexpr int SM_CTX  = GCfg<128, 64, false, 3, 32>::SMEM_BYTES;   // 82944
    cudaFuncSetAttribute(gemm_cp<128, 128, false, 3, 32, false, false>,
                         cudaFuncAttributeMaxDynamicSharedMemorySize, SM_PROJ);
    cudaFuncSetAttribute(gemm_cp<128, 128, false, 3, 32, false, true>,
                         cudaFuncAttributeMaxDynamicSharedMemorySize, SM_PROJ);
    cudaFuncSetAttribute(gemm_cp<128, 128, true, 3, 32, false, false>,
                         cudaFuncAttributeMaxDynamicSharedMemorySize, SM_SCOR);
    cudaFuncSetAttribute(gemm_cp<128, 64, false, 3, 32, true, true>,
                         cudaFuncAttributeMaxDynamicSharedMemorySize, SM_CTX);
    cudaFuncSetAttribute(qkv_cp,
                         cudaFuncAttributeMaxDynamicSharedMemorySize, SM_PROJ);

    // Round all weights to tf32 once per launch
    round_kernel<<<(6 * WLD / 4 + 255) / 256, 256>>>(
        (const float4*)Wq, (float4*)Wq_r, 6 * WLD / 4);
    round_kernel<<<(6 * WLD / 4 + 255) / 256, 256>>>(
        (const float4*)Wk, (float4*)Wk_r, 6 * WLD / 4);
    round_kernel<<<(6 * WLD / 4 + 255) / 256, 256>>>(
        (const float4*)Wv, (float4*)Wv_r, 6 * WLD / 4);
    round_kernel<<<(6 * WLD / 4 + 255) / 256, 256>>>(
        (const float4*)Wo, (float4*)Wo_r, 6 * WLD / 4);
    round_kernel<<<(6 * WF / 4 + 255) / 256, 256>>>(
        (const float4*)W1, (float4*)W1_r, 6 * WF / 4);
    round_kernel<<<(6 * WF / 4 + 255) / 256, 256>>>(
        (const float4*)W2, (float4*)W2_r, 6 * WF / 4);

    pos_kernel<<<(S_ * D_ + 255) / 256, 256>>>(pos);
    add_pos_kernel<<<(X_ELEMS + 255) / 256, 256>>>(x, xr, enc, pos);

    const long CSPLIT = q - tmp;   // z=0 -> tmp, z=1 -> q (partial buffers)

    for (int l = 0; l < L_; l++) {
        float* attn_l = out_attn + (long)l * ATTN_PER_LAYER;

        // Fused Q,K,V projections (rounded outputs)
        qkv_cp<<<dim3(4, 32, 3), 256, SM_PROJ>>>(
            xr, Wq_r + l * WLD, Wk_r + l * WLD, Wv_r + l * WLD, q, k, v);

        // Scores: per (b,h): Q[512,64] @ K^T * (1/8) -> attn region (exact out)
        gemm_cp<128, 128, true, 3, 32, false, false>
            <<<dim3(4, 4, B_ * H_), 256, SM_SCOR>>>(
            q, D_, (long)S_ * D_, DK_,
            k, D_, (long)S_ * D_, DK_,
            attn_l, S_, (long)H_ * S_ * S_, (long)S_ * S_,
            nullptr, DK_, 0.125f, 0, H_);

        // Softmax (in place, applies pad mask)
        softmax_kernel<<<B_ * H_ * S_, 128>>>(attn_l, mask);

        // ctx: per (b,h): attn[512,512] @ V[512,64] (A needs cvt; rounded out)
        gemm_cp<128, 64, false, 3, 32, true, true>
            <<<dim3(1, 4, B_ * H_), 256, SM_CTX>>>(
            attn_l, S_, (long)H_ * S_ * S_, (long)S_ * S_,
            v, D_, (long)S_ * D_, DV_,
            ctx, D_, (long)S_ * D_, DV_,
            nullptr, S_, 1.0f, 0, H_);

        // Wo projection, split-K=2 (256 CTAs; q is free as partial buffer).
        // z=0: K[0,256) -> tmp; z=1: K[256,512) -> q. Reduce fused into LN1.
        gemm_cp<128, 128, false, 3, 32, false, false>
            <<<dim3(4, 32, 2), 256, SM_PROJ>>>(
            ctx, D_, 0, 256,
            Wo_r + l * WLD, D_, 0, (long)256 * D_,
            tmp, D_, 0, CSPLIT,
            nullptr, 256, 1.0f, 0, 2);
        ln3_kernel<<<M_, 256>>>(tmp, q, x, ln1g + l * D_, ln1b + l * D_, x, xr);

        // FFN: relu(xr @ W1) (rounded) -> h1
        gemm_cp<128, 128, false, 3, 32, false, true>
            <<<dim3(16, 32, 1), 256, SM_PROJ>>>(
            xr, D_, 0, 0, W1_r + l * WF, DFF_, 0, 0, h1, DFF_, 0, 0, nullptr, D_,
            1.0f, 1, 1);
        // W2, split-K=2: z=0: K[0,1024) -> tmp; z=1: K[1024,2048) -> q.
        gemm_cp<128, 128, false, 3, 32, false, false>
            <<<dim3(4, 32, 2), 256, SM_PROJ>>>(
            h1, DFF_, 0, 1024,
            W2_r + l * WF, D_, 0, (long)1024 * D_,
            tmp, D_, 0, CSPLIT,
            nullptr, 1024, 1.0f, 0, 2);
        ln3_kernel<<<M_, 256>>>(tmp, q, x, ln2g + l * D_, ln2b + l * D_, x, xr);
    }

    cudaMemcpyAsync(out_x, x, (size_t)X_ELEMS * sizeof(float),
                    cudaMemcpyDeviceToDevice, 0);
}

// round 13
// speedup vs baseline: 1.1146x; 1.0113x over previous
#include <cuda_runtime.h>
#include <math.h>

// Problem constants
#define B_ 8
#define S_ 512
#define D_ 512
#define H_ 8
#define DK_ 64
#define DV_ 64
#define DFF_ 2048
#define L_ 6
#define M_ (B_ * S_)               // 4096 rows
#define X_ELEMS (M_ * D_)          // 2,097,152
#define ATTN_PER_LAYER ((long)B_ * H_ * S_ * S_)  // 16,777,216
#define WLD (D_ * D_)              // 262144
#define WF (D_ * DFF_)             // 1048576

// Device scratch (allocations are forbidden; use __device__ globals)
__device__ float g_x[X_ELEMS];
__device__ float g_xr[X_ELEMS];    // tf32-rounded copy of x (GEMM A input)
__device__ float g_q[X_ELEMS];     // q; reused as split-K partial buffer later
__device__ float g_k[X_ELEMS];
__device__ float g_v[X_ELEMS];
__device__ float g_ctx[X_ELEMS];
__device__ float g_tmp[X_ELEMS];
__device__ float g_h1[M_ * DFF_];
__device__ float g_pos[S_ * D_];
__device__ float g_wr[6 * (4 * WLD + 2 * WF)];  // tf32-rounded weights

// ---------------------------------------------------------------------------
// helpers
// ---------------------------------------------------------------------------
__device__ __forceinline__ unsigned tfc(unsigned x) {
    unsigned r;
    asm("cvt.rna.tf32.f32 %0, %1;" : "=r"(r) : "f"(__uint_as_float(x)));
    return r;
}
__device__ __forceinline__ float frnd(float x) {
    return __uint_as_float(tfc(__float_as_uint(x)));
}

__device__ __forceinline__ void mma8(float* d, const unsigned* a, const unsigned* b) {
    asm volatile(
        "mma.sync.aligned.m16n8k8.row.col.f32.tf32.tf32.f32 "
        "{%0,%1,%2,%3}, {%4,%5,%6,%7}, {%8,%9}, {%0,%1,%2,%3};"
        : "+f"(d[0]), "+f"(d[1]), "+f"(d[2]), "+f"(d[3])
        : "r"(a[0]), "r"(a[1]), "r"(a[2]), "r"(a[3]), "r"(b[0]), "r"(b[1]));
}

__device__ __forceinline__ void ldsm_x4(unsigned* r, unsigned addr) {
    asm volatile("ldmatrix.sync.aligned.m8n8.x4.shared.b16 {%0,%1,%2,%3}, [%4];"
                 : "=r"(r[0]), "=r"(r[1]), "=r"(r[2]), "=r"(r[3]) : "r"(addr));
}

__device__ __forceinline__ void cpa16(unsigned dst, const void* src) {
    asm volatile("cp.async.cg.shared.global [%0], [%1], 16;" :: "r"(dst), "l"(src));
}
__device__ __forceinline__ void cpa_commit() {
    asm volatile("cp.async.commit_group;" ::: "memory");
}
template <int N>
__device__ __forceinline__ void cpa_wait() {
    asm volatile("cp.async.wait_group %0;" :: "n"(N) : "memory");
}

// ---------------------------------------------------------------------------
// tf32 rounding copy (for weights)
// ---------------------------------------------------------------------------
__global__ void round_kernel(const float4* __restrict__ in,
                             float4* __restrict__ out, int n4) {
    int i = blockIdx.x * blockDim.x + threadIdx.x;
    if (i >= n4) return;
    float4 v = in[i];
    v.x = frnd(v.x); v.y = frnd(v.y); v.z = frnd(v.z); v.w = frnd(v.w);
    out[i] = v;
}

// ---------------------------------------------------------------------------
// Positional table (double precision to match numpy float64 path)
// ---------------------------------------------------------------------------
__global__ void pos_kernel(float* __restrict__ pos) {
    int idx = blockIdx.x * blockDim.x + threadIdx.x;
    if (idx >= S_ * D_) return;
    int s = idx >> 9;
    int d = idx & 511;
    double val = 0.0;
    if (s > 0) {
        double ang = (double)s * exp(-log(10000.0) * (2.0 * (double)d / (double)D_));
        val = (d & 1) ? cos(ang) : sin(ang);
    }
    pos[idx] = (float)val;
}

__global__ void add_pos_kernel(float* __restrict__ x, float* __restrict__ xr,
                               const float* __restrict__ enc,
                               const float* __restrict__ pos) {
    int idx = blockIdx.x * blockDim.x + threadIdx.x;
    if (idx >= X_ELEMS) return;
    int sd = idx & (S_ * D_ - 1);
    float v = enc[idx] + pos[sd];
    x[idx] = v;
    xr[idx] = frnd(v);
}

// ---------------------------------------------------------------------------
// TF32 tensor-core GEMM, BK=32 cp.async pipeline, 3 stages.
// 128 threads, 2x2 warp grid, 64x64 warp tiles (halves duplicated smem
// fragment reads vs the 2x4/256-thread layout; doubles per-warp MMA ILP).
//   C[m,n] = alpha * sum_k A[m,k] * (TB ? B[n,k] : B[k,n])  (+ epilogue)
// CVTA: cvt.rna A frags post-ldmatrix. ROUT: round outputs to tf32.
// epi: 0 none, 1 relu, 2 += R.
// ---------------------------------------------------------------------------
#define NTH 128

template <int BM, int BN, bool TB, int STAGES, int BK>
struct GCfg {
    static constexpr int ASTR = BK + 4;
    static constexpr int ABUF = BM * ASTR;
    static constexpr int BSTR = TB ? (BK + 4) : (BN + 8);
    static constexpr int BBUF = TB ? (BN * (BK + 4)) : (BK * (BN + 8));
    static constexpr int SMEM_BYTES = STAGES * (ABUF + BBUF) * 4;
};

template <int BM, int BN, bool TB, int STAGES, int BK, bool CVTA, bool ROUT>
__device__ __forceinline__ void gemm_body(
    float* __restrict__ smem,
    const float* __restrict__ A, int lda,
    const float* __restrict__ Bg, int ldb,
    float* __restrict__ C, int ldc,
    const float* __restrict__ R,
    int K, float alpha, int epi) {
    using CF = GCfg<BM, BN, TB, STAGES, BK>;
    constexpr int ASTR = CF::ASTR, ABUF = CF::ABUF;
    constexpr int BSTR = CF::BSTR, BBUF = CF::BBUF;
    constexpr int KF4 = BK / 4;               // float4 per A row-chunk (8)
    constexpr int RA = NTH / KF4;             // A rows per iteration (16)
    constexpr int AF = BM / RA;               // A cp.async iters (8)
    constexpr int KF4N = BN / 4;              // !TB: float4 per B row
    constexpr int RB = TB ? (NTH / KF4) : (NTH / KF4N);  // B rows per iter
    constexpr int BF = TB ? (BN / RB) : (BK / RB);
    constexpr int WM = BM / 2, WN = BN / 2;
    constexpr int MT = WM / 16, NT = WN / 8;
    constexpr int NKS = BK / 8;

    const int tid = threadIdx.x;
    const int lane = tid & 31;
    const int warp = tid >> 5;
    const int g = lane >> 2;
    const int tg = lane & 3;
    const int wr = warp & 1;
    const int wc = warp >> 1;
    const int m0 = blockIdx.y * BM;
    const int n0 = blockIdx.x * BN;

    float* As = smem;
    float* Bs = smem + STAGES * ABUF;
    const unsigned as_u = (unsigned)__cvta_generic_to_shared(As);
    const unsigned bs_u = (unsigned)__cvta_generic_to_shared(Bs);

    // Affine copy descriptors (single base pointer per operand)
    const int ra = tid / KF4, ca = tid % KF4;
    const float* pA = A + (long)(m0 + ra) * lda + ca * 4;
    const unsigned aoff0 = as_u + (unsigned)(ra * ASTR + ca * 4) * 4u;

    const float* pB;
    unsigned boff0;
    if (TB) {
        const int rb = tid / KF4, cb = tid % KF4;
        pB = Bg + (long)(n0 + rb) * ldb + cb * 4;
        boff0 = bs_u + (unsigned)(rb * BSTR + cb * 4) * 4u;
    } else {
        const int rb = tid / KF4N, cb = tid % KF4N;
        pB = Bg + (long)rb * ldb + n0 + cb * 4;
        boff0 = bs_u + (unsigned)(rb * BSTR + cb * 4) * 4u;
    }
    const long stepB = TB ? BK : (long)BK * ldb;

    int slot_ld = 0;
    auto load_stage = [&]() {
        const unsigned ao = (unsigned)(slot_ld * ABUF) * 4u;
        const unsigned bo = (unsigned)(slot_ld * BBUF) * 4u;
#pragma unroll
        for (int it = 0; it < AF; it++)
            cpa16(aoff0 + ao + (unsigned)(it * RA * ASTR * 4),
                  pA + (long)it * RA * lda);
        pA += BK;
#pragma unroll
        for (int it = 0; it < BF; it++)
            cpa16(boff0 + bo + (unsigned)(it * RB * BSTR * 4),
                  pB + (long)it * RB * ldb);
        pB += stepB;
        slot_ld = (slot_ld + 1 == STAGES) ? 0 : slot_ld + 1;
    };

    const unsigned a_base =
        as_u + (unsigned)(((wr * WM + (lane & 7) + 8 * ((lane >> 3) & 1)) * ASTR +
                           4 * (lane >> 4)) << 2);
    unsigned b_base = 0;
    if (TB) {
        b_base = bs_u + (unsigned)(((wc * WN + (lane & 7) + 8 * (lane >> 4)) * BSTR +
                                    4 * ((lane >> 3) & 1)) << 2);
    }

    float acc[MT][NT][4];
#pragma unroll
    for (int i = 0; i < MT; i++)
#pragma unroll
        for (int j = 0; j < NT; j++)
#pragma unroll
            for (int e = 0; e < 4; e++) acc[i][j][e] = 0.0f;

    const int nch = K / BK;
#pragma unroll
    for (int s = 0; s < STAGES - 1; s++) {
        if (s < nch) load_stage();
        cpa_commit();
    }

    int slot_cmp = 0;
    for (int c = 0; c < nch; c++) {
        cpa_wait<STAGES - 2>();
        __syncthreads();
        const unsigned abp = a_base + (unsigned)(slot_cmp * ABUF) * 4u;
        const unsigned bbp = b_base + (unsigned)(slot_cmp * BBUF) * 4u;
        const float* bbf = Bs + slot_cmp * BBUF;
        slot_cmp = (slot_cmp + 1 == STAGES) ? 0 : slot_cmp + 1;

#pragma unroll
        for (int ks = 0; ks < NKS; ks++) {
            unsigned afr[MT][4], bfr[NT][2];
#pragma unroll
            for (int i = 0; i < MT; i++) {
                ldsm_x4(afr[i], abp + i * (16 * ASTR * 4) + ks * 32);
                if (CVTA) {
#pragma unroll
                    for (int e = 0; e < 4; e++) afr[i][e] = tfc(afr[i][e]);
                }
            }
            if (TB) {
#pragma unroll
                for (int j = 0; j < NT; j += 2)
                    ldsm_x4(&bfr[j][0], bbp + j * (8 * BSTR * 4) + ks * 32);
            } else {
#pragma unroll
                for (int j = 0; j < NT; j++) {
                    int n = wc * WN + j * 8 + g;
                    bfr[j][0] = __float_as_uint(bbf[(ks * 8 + tg) * BSTR + n]);
                    bfr[j][1] = __float_as_uint(bbf[(ks * 8 + 4 + tg) * BSTR + n]);
                }
            }
#pragma unroll
            for (int i = 0; i < MT; i++)
#pragma unroll
                for (int j = 0; j < NT; j++) mma8(acc[i][j], afr[i], bfr[j]);
        }

        if (c + STAGES - 1 < nch) load_stage();
        cpa_commit();
    }

    // Epilogue
#pragma unroll
    for (int i = 0; i < MT; i++) {
        int r0 = m0 + wr * WM + i * 16 + g;
#pragma unroll
        for (int j = 0; j < NT; j++) {
            int col = n0 + wc * WN + j * 8 + tg * 2;
            float v0 = acc[i][j][0] * alpha;
            float v1 = acc[i][j][1] * alpha;
            float v2 = acc[i][j][2] * alpha;
            float v3 = acc[i][j][3] * alpha;
            if (epi == 1) {
                v0 = fmaxf(v0, 0.0f); v1 = fmaxf(v1, 0.0f);
                v2 = fmaxf(v2, 0.0f); v3 = fmaxf(v3, 0.0f);
            } else if (epi == 2) {
                v0 += R[(long)r0 * ldc + col];
                v1 += R[(long)r0 * ldc + col + 1];
                v2 += R[(long)(r0 + 8) * ldc + col];
                v3 += R[(long)(r0 + 8) * ldc + col + 1];
            }
            if (ROUT) {
                v0 = frnd(v0); v1 = frnd(v1); v2 = frnd(v2); v3 = frnd(v3);
            }
            float2 p01; p01.x = v0; p01.y = v1;
            float2 p23; p23.x = v2; p23.y = v3;
            *reinterpret_cast<float2*>(&C[(long)r0 * ldc + col]) = p01;
            *reinterpret_cast<float2*>(&C[(long)(r0 + 8) * ldc + col]) = p23;
        }
    }
}

template <int BM, int BN, bool TB, int STAGES, int BK, bool CVTA, bool ROUT>
__global__ void __launch_bounds__(NTH, 2)
gemm_cp(const float* __restrict__ A, int lda, long sAb, long sAh,
        const float* __restrict__ Bg, int ldb, long sBb, long sBh,
        float* __restrict__ C, int ldc, long sCb, long sCh,
        const float* __restrict__ R,
        int K, float alpha, int epi, int hdiv) {
    extern __shared__ float smem[];
    const int z = blockIdx.z;
    const int zb = z / hdiv;
    const int zh = z % hdiv;
    gemm_body<BM, BN, TB, STAGES, BK, CVTA, ROUT>(
        smem,
        A + (long)zb * sAb + (long)zh * sAh, lda,
        Bg + (long)zb * sBb + (long)zh * sBh, ldb,
        C + (long)zb * sCb + (long)zh * sCh, ldc,
        R, K, alpha, epi);
}

// Fused Q/K/V projection: blockIdx.z selects the weight/output pair.
__global__ void __launch_bounds__(NTH, 2)
qkv_cp(const float* __restrict__ x,
       const float* __restrict__ Wq, const float* __restrict__ Wk,
       const float* __restrict__ Wv,
       float* __restrict__ q, float* __restrict__ k, float* __restrict__ v) {
    extern __shared__ float smem[];
    const int z = blockIdx.z;
    const float* W = (z == 0) ? Wq : (z == 1) ? Wk : Wv;
    float* C = (z == 0) ? q : (z == 1) ? k : v;
    gemm_body<128, 128, false, 3, 32, false, true>(smem, x, D_, W, D_, C, D_,
                                                   nullptr, D_, 1.0f, 0);
}

// ---------------------------------------------------------------------------
// In-place row softmax; 128 threads, float4 per thread, shuffle reductions.
// ---------------------------------------------------------------------------
__global__ void __launch_bounds__(128)
softmax_kernel(float* __restrict__ attn, const int* __restrict__ mask) {
    const int row = blockIdx.x;
    const int b = row >> 12;
    const int t = threadIdx.x;
    float4* p = reinterpret_cast<float4*>(attn + (long)row * S_);
    const int4* mp = reinterpret_cast<const int4*>(mask + b * S_);

    float4 v = p[t];
    int4 mm = mp[t];
    if (mm.x == 0) v.x = -1e9f;
    if (mm.y == 0) v.y = -1e9f;
    if (mm.z == 0) v.z = -1e9f;
    if (mm.w == 0) v.w = -1e9f;

    float mx = fmaxf(fmaxf(v.x, v.y), fmaxf(v.z, v.w));
#pragma unroll
    for (int o = 16; o; o >>= 1) mx = fmaxf(mx, __shfl_xor_sync(0xffffffffu, mx, o));
    __shared__ float sm[4], ss[4];
    if ((t & 31) == 0) sm[t >> 5] = mx;
    __syncthreads();
    mx = fmaxf(fmaxf(sm[0], sm[1]), fmaxf(sm[2], sm[3]));

    float4 e;
    e.x = __expf(v.x - mx);
    e.y = __expf(v.y - mx);
    e.z = __expf(v.z - mx);
    e.w = __expf(v.w - mx);
    float s = e.x + e.y + e.z + e.w;
#pragma unroll
    for (int o = 16; o; o >>= 1) s += __shfl_xor_sync(0xffffffffu, s, o);
    if ((t & 31) == 0) ss[t >> 5] = s;
    __syncthreads();
    s = ss[0] + ss[1] + ss[2] + ss[3];
    const float inv = 1.0f / s;
    e.x *= inv; e.y *= inv; e.z *= inv; e.w *= inv;
    p[t] = e;
}

// ---------------------------------------------------------------------------
// LayerNorm over last dim (512); input = p0 + p1 + residual (split-K reduce
// fused); dual output (fp32 + tf32-rounded).
// ---------------------------------------------------------------------------
__global__ void ln3_kernel(const float* __restrict__ p0,
                           const float* __restrict__ p1,
                           const float* __restrict__ res,
                           const float* __restrict__ g,
                           const float* __restrict__ bb,
                           float* __restrict__ out,
                           float* __restrict__ outr) {
    const int row = blockIdx.x;
    const long base = (long)row * D_;
    const int t = threadIdx.x;

    float x0 = (p0[base + t] + p1[base + t]) + res[base + t];
    float x1 = (p0[base + t + 256] + p1[base + t + 256]) + res[base + t + 256];

    __shared__ float red[256];
    red[t] = x0 + x1;
    __syncthreads();
#pragma unroll
    for (int s = 128; s > 0; s >>= 1) {
        if (t < s) red[t] += red[t + s];
        __syncthreads();
    }
    const float mean = red[0] * (1.0f / D_);
    __syncthreads();

    float d0 = x0 - mean;
    float d1 = x1 - mean;
    red[t] = d0 * d0 + d1 * d1;
    __syncthreads();
#pragma unroll
    for (int s = 128; s > 0; s >>= 1) {
        if (t < s) red[t] += red[t + s];
        __syncthreads();
    }
    const float var = red[0] * (1.0f / D_);
    const float rs = rsqrtf(var + 1e-5f);

    float o0 = d0 * rs * g[t] + bb[t];
    float o1 = d1 * rs * g[t + 256] + bb[t + 256];
    out[base + t] = o0;
    out[base + t + 256] = o1;
    outr[base + t] = frnd(o0);
    outr[base + t + 256] = frnd(o1);
}

// ---------------------------------------------------------------------------
extern "C" void kernel_launch(void* const* d_in, const int* in_sizes, int n_in,
                              void* d_out, int out_size) {
    const float* enc = (const float*)d_in[0];
    const int* mask = (const int*)d_in[1];
    const float* Wq = (const float*)d_in[2];
    const float* Wk = (const float*)d_in[3];
    const float* Wv = (const float*)d_in[4];
    const float* Wo = (const float*)d_in[5];
    const float* ln1g = (const float*)d_in[6];
    const float* ln1b = (const float*)d_in[7];
    const float* W1 = (const float*)d_in[8];
    const float* W2 = (const float*)d_in[9];
    const float* ln2g = (const float*)d_in[10];
    const float* ln2b = (const float*)d_in[11];

    float *x, *xr, *q, *k, *v, *ctx, *tmp, *h1, *pos, *wr;
    cudaGetSymbolAddress((void**)&x, g_x);
    cudaGetSymbolAddress((void**)&xr, g_xr);
    cudaGetSymbolAddress((void**)&q, g_q);
    cudaGetSymbolAddress((void**)&k, g_k);
    cudaGetSymbolAddress((void**)&v, g_v);
    cudaGetSymbolAddress((void**)&ctx, g_ctx);
    cudaGetSymbolAddress((void**)&tmp, g_tmp);
    cudaGetSymbolAddress((void**)&h1, g_h1);
    cudaGetSymbolAddress((void**)&pos, g_pos);
    cudaGetSymbolAddress((void**)&wr, g_wr);

    float* Wq_r = wr;
    float* Wk_r = Wq_r + 6 * WLD;
    float* Wv_r = Wk_r + 6 * WLD;
    float* Wo_r = Wv_r + 6 * WLD;
    float* W1_r = Wo_r + 6 * WLD;
    float* W2_r = W1_r + 6 * WF;

    float* out_x = (float*)d_out;
    float* out_attn = out_x + X_ELEMS;

    constexpr int SM_PROJ = GCfg<128, 128, false, 3, 32>::SMEM_BYTES;  // 107520
    constexpr int SM_SCOR = GCfg<128, 128, true, 3, 32>::SMEM_BYTES;   // 110592
    constexpr int SM_CTX  = GCfg<128, 64, false, 3, 32>::SMEM_BYTES;   // 82944
    cudaFuncSetAttribute(gemm_cp<128, 128, false, 3, 32, false, false>,
                         cudaFuncAttributeMaxDynamicSharedMemorySize, SM_PROJ);
    cudaFuncSetAttribute(gemm_cp<128, 128, false, 3, 32, false, true>,
                         cudaFuncAttributeMaxDynamicSharedMemorySize, SM_PROJ);
    cudaFuncSetAttribute(gemm_cp<128, 128, true, 3, 32, false, false>,
                         cudaFuncAttributeMaxDynamicSharedMemorySize, SM_SCOR);
    cudaFuncSetAttribute(gemm_cp<128, 64, false, 3, 32, true, true>,
                         cudaFuncAttributeMaxDynamicSharedMemorySize, SM_CTX);
    cudaFuncSetAttribute(qkv_cp,
                         cudaFuncAttributeMaxDynamicSharedMemorySize, SM_PROJ);

    // Round all weights to tf32 once per launch
    round_kernel<<<(6 * WLD / 4 + 255) / 256, 256>>>(
        (const float4*)Wq, (float4*)Wq_r, 6 * WLD / 4);
    round_kernel<<<(6 * WLD / 4 + 255) / 256, 256>>>(
        (const float4*)Wk, (float4*)Wk_r, 6 * WLD / 4);
    round_kernel<<<(6 * WLD / 4 + 255) / 256, 256>>>(
        (const float4*)Wv, (float4*)Wv_r, 6 * WLD / 4);
    round_kernel<<<(6 * WLD / 4 + 255) / 256, 256>>>(
        (const float4*)Wo, (float4*)Wo_r, 6 * WLD / 4);
    round_kernel<<<(6 * WF / 4 + 255) / 256, 256>>>(
        (const float4*)W1, (float4*)W1_r, 6 * WF / 4);
    round_kernel<<<(6 * WF / 4 + 255) / 256, 256>>>(
        (const float4*)W2, (float4*)W2_r, 6 * WF / 4);

    pos_kernel<<<(S_ * D_ + 255) / 256, 256>>>(pos);
    add_pos_kernel<<<(X_ELEMS + 255) / 256, 256>>>(x, xr, enc, pos);

    const long CSPLIT = q - tmp;   // z=0 -> tmp, z=1 -> q (partial buffers)

    for (int l = 0; l < L_; l++) {
        float* attn_l = out_attn + (long)l * ATTN_PER_LAYER;

        // Fused Q,K,V projections (rounded outputs)
        qkv_cp<<<dim3(4, 32, 3), NTH, SM_PROJ>>>(
            xr, Wq_r + l * WLD, Wk_r + l * WLD, Wv_r + l * WLD, q, k, v);

        // Scores: per (b,h): Q[512,64] @ K^T * (1/8) -> attn region (exact out)
        gemm_cp<128, 128, true, 3, 32, false, false>
            <<<dim3(4, 4, B_ * H_), NTH, SM_SCOR>>>(
            q, D_, (long)S_ * D_, DK_,
            k, D_, (long)S_ * D_, DK_,
            attn_l, S_, (long)H_ * S_ * S_, (long)S_ * S_,
            nullptr, DK_, 0.125f, 0, H_);

        // Softmax (in place, applies pad mask)
        softmax_kernel<<<B_ * H_ * S_, 128>>>(attn_l, mask);

        // ctx: per (b,h): attn[512,512] @ V[512,64] (A needs cvt; rounded out)
        gemm_cp<128, 64, false, 3, 32, true, true>
            <<<dim3(1, 4, B_ * H_), NTH, SM_CTX>>>(
            attn_l, S_, (long)H_ * S_ * S_, (long)S_ * S_,
            v, D_, (long)S_ * D_, DV_,
            ctx, D_, (long)S_ * D_, DV_,
            nullptr, S_, 1.0f, 0, H_);

        // Wo projection, split-K=2 (q is free as partial buffer).
        // z=0: K[0,256) -> tmp; z=1: K[256,512) -> q. Reduce fused into LN1.
        gemm_cp<128, 128, false, 3, 32, false, false>
            <<<dim3(4, 32, 2), NTH, SM_PROJ>>>(
            ctx, D_, 0, 256,
            Wo_r + l * WLD, D_, 0, (long)256 * D_,
            tmp, D_, 0, CSPLIT,
            nullptr, 256, 1.0f, 0, 2);
        ln3_kernel<<<M_, 256>>>(tmp, q, x, ln1g + l * D_, ln1b + l * D_, x, xr);

        // FFN: relu(xr @ W1) (rounded) -> h1
        gemm_cp<128, 128, false, 3, 32, false, true>
            <<<dim3(16, 32, 1), NTH, SM_PROJ>>>(
            xr, D_, 0, 0, W1_r + l * WF, DFF_, 0, 0, h1, DFF_, 0, 0, nullptr, D_,
            1.0f, 1, 1);
        // W2, split-K=2: z=0: K[0,1024) -> tmp; z=1: K[1024,2048) -> q.
        gemm_cp<128, 128, false, 3, 32, false, false>
            <<<dim3(4, 32, 2), NTH, SM_PROJ>>>(
            h1, DFF_, 0, 1024,
            W2_r + l * WF, D_, 0, (long)1024 * D_,
            tmp, D_, 0, CSPLIT,
            nullptr, 1024, 1.0f, 0, 2);
        ln3_kernel<<<M_, 256>>>(tmp, q, x, ln2g + l * D_, ln2b + l * D_, x, xr);
    }

    cudaMemcpyAsync(out_x, x, (size_t)X_ELEMS * sizeof(float),
                    cudaMemcpyDeviceToDevice, 0);
}